// round 15
// baseline (speedup 1.0000x reference)
#include <cuda_runtime.h>
#include <cstdint>

// HybridLoss: smooth_l1(preds,targets) + 0.5*(1 - mean(box_overlap))
// preds, targets: [2000000, 10] float32 row-major. Output: 1 float scalar.
//
// cp.async (LDGSTS) double-buffer, 256 thr/CTA, 256-row tiles, 4 CTA/SM.
// Every thread issues exactly 5 contiguous 16B chunks per tile (lane-dense,
// minimal L1tex wavefronts) and consumes exactly 1 row per tile (no idle
// consumers). Issue-before-wait keeps one full tile in flight per CTA.

#define NROWS 2000000
#define THREADS 256
#define NBLOCKS 592                                   // 148 SMs * 4 CTAs
#define STAGES 2
#define TILE_ROWS 256
#define ABYTES (TILE_ROWS * 40)                       // 10240 B per array
#define STAGE_BYTES (2 * ABYTES)                      // 20480 B
#define NTILES ((NROWS + TILE_ROWS - 1) / TILE_ROWS)  // 7813 (last = 128 rows)
#define SMEM_DYN (STAGES * STAGE_BYTES)               // 40960 B
#define CHUNKS (STAGE_BYTES / 16)                     // 1280 = 5 * 256
#define PCHUNKS (ABYTES / 16)                         // 640
#define EPSF 1e-6f

__device__ double g_acc[2] = {0.0, 0.0};
__device__ unsigned int g_ticket = 0;

__device__ __forceinline__ uint32_t smem_u32(const void* p) {
    return (uint32_t)__cvta_generic_to_shared(p);
}
__device__ __forceinline__ void cp16(uint32_t dst, const void* src) {
    asm volatile("cp.async.cg.shared.global [%0], [%1], 16;" :: "r"(dst), "l"(src));
}
__device__ __forceinline__ void cp_commit() {
    asm volatile("cp.async.commit_group;" ::: "memory");
}
template <int N>
__device__ __forceinline__ void cp_wait_group() {
    asm volatile("cp.async.wait_group %0;" :: "n"(N) : "memory");
}

// Issue one tile: 1280 contiguous 16B chunks, 5 per thread, no divergence
// except the preds/targets split and the last-tile bounds guard.
__device__ __forceinline__ void issue_stage(char* stage_base,
                                            const char* __restrict__ preds,
                                            const char* __restrict__ targets,
                                            int tile, int tid)
{
    const size_t tbase = (size_t)tile * ABYTES;
    const size_t limit = (size_t)NROWS * 40;
    const uint32_t dst0 = smem_u32(stage_base);
    #pragma unroll
    for (int j = 0; j < 5; j++) {
        const int idx = tid + j * THREADS;            // 0..1279
        if (idx < PCHUNKS) {
            const size_t off = tbase + (size_t)idx * 16;
            if (off < limit) cp16(dst0 + (uint32_t)idx * 16, preds + off);
        } else {
            const size_t off = tbase + (size_t)(idx - PCHUNKS) * 16;
            if (off < limit) cp16(dst0 + (uint32_t)idx * 16, targets + off);
        }
    }
}

__device__ __forceinline__ void row_math(const char* __restrict__ prow,
                                         const char* __restrict__ trow,
                                         float& l1_acc, float& ov_acc)
{
    float p[10], t[10];
    const float2* rp = reinterpret_cast<const float2*>(prow);
    const float2* rt = reinterpret_cast<const float2*>(trow);
    #pragma unroll
    for (int j = 0; j < 5; j++) {
        float2 a = rp[j]; p[2*j] = a.x; p[2*j+1] = a.y;
        float2 b = rt[j]; t[2*j] = b.x; t[2*j+1] = b.y;
    }

    // smooth L1, select-free
    #pragma unroll
    for (int j = 0; j < 10; j++) {
        float d  = p[j] - t[j];
        float ad = fabsf(d);
        float m  = fminf(ad, 1.0f);
        l1_acc = fmaf(m, fmaf(-0.5f, m, ad), l1_acc);
    }

    // raw quaternions (no normalization)
    const float px = p[6], py = p[7], pz = p[8], pw = p[9];
    const float gx = t[6], gy = t[7], gz = t[8], gw = t[9];
    const float Ap = px*px + py*py + pz*pz + pw*pw;
    const float Ag = gx*gx + gy*gy + gz*gz + gw*gw;
    const float rpg = __fdividef(1.0f, Ap * Ag);
    const float sp  = 0.5f * Ag * rpg;   // 0.5/Ap
    const float sg  = 0.5f * Ap * rpg;   // 0.5/Ag

    const float dq = px*gx + py*gy + pz*gz + pw*gw;
    const float rot_align = fmaxf(fmaf(4.0f * dq * dq, rpg, -1.0f) * (1.0f/3.0f), 0.0f);

    const float dpx = p[3], dpy = p[4], dpz = p[5];
    const float dgx = t[3], dgy = t[4], dgz = t[5];

    float num = 1.0f, den = 1.0f;
    {
        float mp = (Ap - 2.0f*(py*py + pz*pz))*dpx + 2.0f*(px*py + pz*pw)*dpy + 2.0f*(px*pz - py*pw)*dpz;
        float mg = (Ag - 2.0f*(gy*gy + gz*gz))*dgx + 2.0f*(gx*gy + gz*gw)*dgy + 2.0f*(gx*gz - gy*gw)*dgz;
        float pe = sp * fabsf(mp), ge = sg * fabsf(mg);
        float cd = fabsf(p[0] - t[0]);
        num *= fmaxf(2.0f * fminf(pe, ge) - cd, 0.0f);
        den *= pe + ge + EPSF;
    }
    {
        float mp = 2.0f*(px*py - pz*pw)*dpx + (Ap - 2.0f*(px*px + pz*pz))*dpy + 2.0f*(py*pz + px*pw)*dpz;
        float mg = 2.0f*(gx*gy - gz*gw)*dgx + (Ag - 2.0f*(gx*gx + gz*gz))*dgy + 2.0f*(gy*gz + gx*gw)*dgz;
        float pe = sp * fabsf(mp), ge = sg * fabsf(mg);
        float cd = fabsf(p[1] - t[1]);
        num *= fmaxf(2.0f * fminf(pe, ge) - cd, 0.0f);
        den *= pe + ge + EPSF;
    }
    {
        float mp = 2.0f*(px*pz + py*pw)*dpx + 2.0f*(py*pz - px*pw)*dpy + (Ap - 2.0f*(px*px + py*py))*dpz;
        float mg = 2.0f*(gx*gz + gy*gw)*dgx + 2.0f*(gy*gz - gx*gw)*dgy + (Ag - 2.0f*(gx*gx + gy*gy))*dgz;
        float pe = sp * fabsf(mp), ge = sg * fabsf(mg);
        float cd = fabsf(p[2] - t[2]);
        num *= fmaxf(2.0f * fminf(pe, ge) - cd, 0.0f);
        den *= pe + ge + EPSF;
    }
    ov_acc += __fdividef(num * rot_align, den);
}

__global__ __launch_bounds__(THREADS, 4) void hl_fused_kernel(
    const float* __restrict__ preds,
    const float* __restrict__ targets,
    float* __restrict__ out)
{
    extern __shared__ char dynbuf[];                 // STAGES * STAGE_BYTES
    const int tid = threadIdx.x;
    const int bid = blockIdx.x;

    const char* pc = (const char*)preds;
    const char* tc = (const char*)targets;

    // prologue: issue tile for stage 0
    if (bid < NTILES)
        issue_stage(dynbuf, pc, tc, bid, tid);
    cp_commit();

    float l1_sum = 0.0f;
    float ov     = 0.0f;

    int k = 0;
    for (int tile = bid; tile < NTILES; tile += NBLOCKS, k++) {
        // issue next tile into the other buffer (freed by the trailing
        // __syncthreads of the previous iteration)
        const int tn = tile + NBLOCKS;
        if (tn < NTILES)
            issue_stage(dynbuf + ((k + 1) & 1) * STAGE_BYTES, pc, tc, tn, tid);
        cp_commit();

        cp_wait_group<1>();                           // tile k's group done
        __syncthreads();

        char* stage = dynbuf + (k & 1) * STAGE_BYTES;
        const int rows = min(TILE_ROWS, NROWS - tile * TILE_ROWS);
        if (tid < rows)
            row_math(stage + tid * 40, stage + ABYTES + tid * 40, l1_sum, ov);

        __syncthreads();                              // release buffer k&1
    }

    // ---- block reduction ----
    #pragma unroll
    for (int off = 16; off > 0; off >>= 1) {
        l1_sum += __shfl_down_sync(0xFFFFFFFFu, l1_sum, off);
        ov     += __shfl_down_sync(0xFFFFFFFFu, ov, off);
    }
    __shared__ float warp_l1[THREADS / 32];
    __shared__ float warp_ov[THREADS / 32];
    const int lane = tid & 31;
    const int wid  = tid >> 5;
    if (lane == 0) { warp_l1[wid] = l1_sum; warp_ov[wid] = ov; }
    __syncthreads();

    if (wid == 0) {
        float a = (lane < THREADS / 32) ? warp_l1[lane] : 0.0f;
        float b = (lane < THREADS / 32) ? warp_ov[lane] : 0.0f;
        #pragma unroll
        for (int off = 4; off > 0; off >>= 1) {
            a += __shfl_down_sync(0xFFFFFFFFu, a, off);
            b += __shfl_down_sync(0xFFFFFFFFu, b, off);
        }
        if (lane == 0) {
            atomicAdd(&g_acc[0], (double)a);
            atomicAdd(&g_acc[1], (double)b);
            __threadfence();
            unsigned int ticket = atomicAdd(&g_ticket, 1u);
            if (ticket == (unsigned int)(NBLOCKS - 1)) {
                double s0 = *((volatile double*)&g_acc[0]);
                double s1 = *((volatile double*)&g_acc[1]);
                double param_loss = s0 / ((double)NROWS * 10.0);
                double mean_ov    = s1 / (double)NROWS;
                out[0] = (float)(param_loss + 0.5 * (1.0 - mean_ov));
                *((volatile double*)&g_acc[0]) = 0.0;
                *((volatile double*)&g_acc[1]) = 0.0;
                __threadfence();
                g_ticket = 0;
                __threadfence();
            }
        }
    }
}

extern "C" void kernel_launch(void* const* d_in, const int* in_sizes, int n_in,
                              void* d_out, int out_size) {
    const float* preds   = (const float*)d_in[0];
    const float* targets = (const float*)d_in[1];
    float* out = (float*)d_out;

    static bool attr_set = false;
    if (!attr_set) {
        cudaFuncSetAttribute(hl_fused_kernel,
                             cudaFuncAttributeMaxDynamicSharedMemorySize, SMEM_DYN);
        attr_set = true;
    }
    hl_fused_kernel<<<NBLOCKS, THREADS, SMEM_DYN>>>(preds, targets, out);
}

// round 16
// speedup vs baseline: 1.0512x; 1.0512x over previous
#include <cuda_runtime.h>

// HybridLoss: smooth_l1(preds,targets) + 0.5*(1 - mean(box_overlap))
// preds, targets: [2000000, 10] float32 row-major. Output: 1 float scalar.
//
// Persistent kernel (592 CTAs x 256 thr, 4 CTA/SM) + DYNAMIC work stealing:
// 256-row units handed out by a global atomic counter (2-deep index queue,
// atomic latency hidden under math), distance-1 register prefetch.

#define NROWS 2000000
#define THREADS 256
#define NBLOCKS 592                                   // 148 SMs * 4 CTAs
#define UNIT_ROWS 256
#define NUNITS ((NROWS + UNIT_ROWS - 1) / UNIT_ROWS)  // 7813 (last = 128 rows)
#define EPSF 1e-6f

__device__ double g_acc[2] = {0.0, 0.0};
__device__ unsigned int g_ticket = 0;
__device__ unsigned int g_work = NBLOCKS;             // units 0..NBLOCKS-1 pre-assigned

__device__ __forceinline__ void load_row(const float2* __restrict__ p2,
                                         const float2* __restrict__ t2,
                                         int row, float2* bp, float2* bt)
{
    const float2* rp = p2 + (size_t)row * 5;   // 40B rows -> 5 float2
    const float2* rt = t2 + (size_t)row * 5;
    #pragma unroll
    for (int j = 0; j < 5; j++) { bp[j] = rp[j]; bt[j] = rt[j]; }
}

__device__ __forceinline__ void row_math(const float2* __restrict__ bp,
                                         const float2* __restrict__ bt,
                                         float& l1_acc, float& ov_acc)
{
    float p[10], t[10];
    #pragma unroll
    for (int j = 0; j < 5; j++) {
        p[2*j] = bp[j].x; p[2*j+1] = bp[j].y;
        t[2*j] = bt[j].x; t[2*j+1] = bt[j].y;
    }

    // smooth L1, select-free
    #pragma unroll
    for (int j = 0; j < 10; j++) {
        float d  = p[j] - t[j];
        float ad = fabsf(d);
        float m  = fminf(ad, 1.0f);
        l1_acc = fmaf(m, fmaf(-0.5f, m, ad), l1_acc);
    }

    // raw quaternions (no normalization)
    const float px = p[6], py = p[7], pz = p[8], pw = p[9];
    const float gx = t[6], gy = t[7], gz = t[8], gw = t[9];
    const float Ap = px*px + py*py + pz*pz + pw*pw;
    const float Ag = gx*gx + gy*gy + gz*gz + gw*gw;
    const float rpg = __fdividef(1.0f, Ap * Ag);
    const float sp  = 0.5f * Ag * rpg;   // 0.5/Ap
    const float sg  = 0.5f * Ap * rpg;   // 0.5/Ag

    const float dq = px*gx + py*gy + pz*gz + pw*gw;
    const float rot_align = fmaxf(fmaf(4.0f * dq * dq, rpg, -1.0f) * (1.0f/3.0f), 0.0f);

    const float dpx = p[3], dpy = p[4], dpz = p[5];
    const float dgx = t[3], dgy = t[4], dgz = t[5];

    float num = 1.0f, den = 1.0f;
    {
        float mp = (Ap - 2.0f*(py*py + pz*pz))*dpx + 2.0f*(px*py + pz*pw)*dpy + 2.0f*(px*pz - py*pw)*dpz;
        float mg = (Ag - 2.0f*(gy*gy + gz*gz))*dgx + 2.0f*(gx*gy + gz*gw)*dgy + 2.0f*(gx*gz - gy*gw)*dgz;
        float pe = sp * fabsf(mp), ge = sg * fabsf(mg);
        float cd = fabsf(p[0] - t[0]);
        num *= fmaxf(2.0f * fminf(pe, ge) - cd, 0.0f);
        den *= pe + ge + EPSF;
    }
    {
        float mp = 2.0f*(px*py - pz*pw)*dpx + (Ap - 2.0f*(px*px + pz*pz))*dpy + 2.0f*(py*pz + px*pw)*dpz;
        float mg = 2.0f*(gx*gy - gz*gw)*dgx + (Ag - 2.0f*(gx*gx + gz*gz))*dgy + 2.0f*(gy*gz + gx*gw)*dgz;
        float pe = sp * fabsf(mp), ge = sg * fabsf(mg);
        float cd = fabsf(p[1] - t[1]);
        num *= fmaxf(2.0f * fminf(pe, ge) - cd, 0.0f);
        den *= pe + ge + EPSF;
    }
    {
        float mp = 2.0f*(px*pz + py*pw)*dpx + 2.0f*(py*pz - px*pw)*dpy + (Ap - 2.0f*(px*px + py*py))*dpz;
        float mg = 2.0f*(gx*gz + gy*gw)*dgx + 2.0f*(gy*gz - gx*gw)*dgy + (Ag - 2.0f*(gx*gx + gy*gy))*dgz;
        float pe = sp * fabsf(mp), ge = sg * fabsf(mg);
        float cd = fabsf(p[2] - t[2]);
        num *= fmaxf(2.0f * fminf(pe, ge) - cd, 0.0f);
        den *= pe + ge + EPSF;
    }
    ov_acc += __fdividef(num * rot_align, den);
}

__global__ __launch_bounds__(THREADS, 4) void hl_fused_kernel(
    const float* __restrict__ preds,
    const float* __restrict__ targets,
    float* __restrict__ out)
{
    __shared__ unsigned int s_idx[2];   // double-buffered next-next unit index

    const int tid = threadIdx.x;
    const int bid = blockIdx.x;

    const float2* __restrict__ p2 = reinterpret_cast<const float2*>(preds);
    const float2* __restrict__ t2 = reinterpret_cast<const float2*>(targets);

    float l1_sum = 0.0f;
    float ov     = 0.0f;

    // unit 0 for this CTA is pre-assigned: u_cur = bid
    unsigned int u_cur = (unsigned int)bid;

    // load current buffer
    float2 cp[5], ct[5];
    {
        int row = (int)u_cur * UNIT_ROWS + tid;
        if (row < NROWS) load_row(p2, t2, row, cp, ct);
    }

    // fetch u_next (unit k+1)
    if (tid == 0) s_idx[0] = atomicAdd(&g_work, 1u);
    __syncthreads();
    unsigned int u_next = s_idx[0];

    int k = 0;
    while (u_cur < NUNITS) {
        // 1) prefetch next unit's row into registers (address known)
        float2 np[5], nt[5];
        const bool have_next = (u_next < NUNITS);
        if (have_next) {
            int nrow = (int)u_next * UNIT_ROWS + tid;
            if (nrow < NROWS) load_row(p2, t2, nrow, np, nt);
        }

        // 2) thread 0 fetches unit k+2 (latency hides under math)
        if (tid == 0) s_idx[(k + 1) & 1] = atomicAdd(&g_work, 1u);

        // 3) compute current unit
        {
            int row = (int)u_cur * UNIT_ROWS + tid;
            if (row < NROWS) row_math(cp, ct, l1_sum, ov);
        }

        // 4) publish the fetched index; also separates the s_idx slot's
        //    reads (this iter) from its next write (two iters later)
        __syncthreads();

        u_cur  = u_next;
        u_next = s_idx[(k + 1) & 1];
        #pragma unroll
        for (int j = 0; j < 5; j++) { cp[j] = np[j]; ct[j] = nt[j]; }
        k++;
    }

    // ---- block reduction ----
    #pragma unroll
    for (int off = 16; off > 0; off >>= 1) {
        l1_sum += __shfl_down_sync(0xFFFFFFFFu, l1_sum, off);
        ov     += __shfl_down_sync(0xFFFFFFFFu, ov, off);
    }
    __shared__ float warp_l1[THREADS / 32];
    __shared__ float warp_ov[THREADS / 32];
    const int lane = tid & 31;
    const int wid  = tid >> 5;
    if (lane == 0) { warp_l1[wid] = l1_sum; warp_ov[wid] = ov; }
    __syncthreads();

    if (wid == 0) {
        float a = (lane < THREADS / 32) ? warp_l1[lane] : 0.0f;
        float b = (lane < THREADS / 32) ? warp_ov[lane] : 0.0f;
        #pragma unroll
        for (int off = 4; off > 0; off >>= 1) {
            a += __shfl_down_sync(0xFFFFFFFFu, a, off);
            b += __shfl_down_sync(0xFFFFFFFFu, b, off);
        }
        if (lane == 0) {
            atomicAdd(&g_acc[0], (double)a);
            atomicAdd(&g_acc[1], (double)b);
            __threadfence();
            unsigned int ticket = atomicAdd(&g_ticket, 1u);
            if (ticket == (unsigned int)(NBLOCKS - 1)) {
                double s0 = *((volatile double*)&g_acc[0]);
                double s1 = *((volatile double*)&g_acc[1]);
                double param_loss = s0 / ((double)NROWS * 10.0);
                double mean_ov    = s1 / (double)NROWS;
                out[0] = (float)(param_loss + 0.5 * (1.0 - mean_ov));
                // self-reset for next graph replay
                *((volatile double*)&g_acc[0]) = 0.0;
                *((volatile double*)&g_acc[1]) = 0.0;
                g_work = NBLOCKS;
                __threadfence();
                g_ticket = 0;
                __threadfence();
            }
        }
    }
}

extern "C" void kernel_launch(void* const* d_in, const int* in_sizes, int n_in,
                              void* d_out, int out_size) {
    const float* preds   = (const float*)d_in[0];
    const float* targets = (const float*)d_in[1];
    float* out = (float*)d_out;

    hl_fused_kernel<<<NBLOCKS, THREADS>>>(preds, targets, out);
}